// round 14
// baseline (speedup 1.0000x reference)
#include <cuda_runtime.h>

typedef unsigned long long ull;
typedef unsigned int uint;

#define BB   64
#define CC   768
#define HW   24
#define NPIX 576
#define HID  768
#define KS1  12         // gemm1 K-splits (KC1 = 64)
#define KC1  64
#define KS2  24         // gemm2 K-splits (KC2 = 32)
#define KC2  32
#define NIT8 (BB * 96)  // pool items

// ---------------- device scratch ----------------
__device__ __align__(16) ull   g_featp[BB * CC];
__device__ __align__(16) float g_p1[KS1][BB * HID];
__device__ __align__(16) float g_p2[KS2][BB * HID];

// ---------------- packed fp32 helpers ----------------
__device__ __forceinline__ ull ffma2(ull a, ull b, ull c) {
    ull d;
    asm("fma.rn.f32x2 %0, %1, %2, %3;" : "=l"(d) : "l"(a), "l"(b), "l"(c));
    return d;
}
__device__ __forceinline__ ull fadd2(ull a, ull b) {
    ull d;
    asm("add.rn.f32x2 %0, %1, %2;" : "=l"(d) : "l"(a), "l"(b));
    return d;
}
__device__ __forceinline__ ull dup2(float x) {
    ull d;
    asm("mov.b64 %0, {%1, %1};" : "=l"(d) : "f"(x));
    return d;
}
__device__ __forceinline__ ull pack2(float lo, float hi) {
    ull d;
    asm("mov.b64 %0, {%1, %2};" : "=l"(d) : "f"(lo), "f"(hi));
    return d;
}
__device__ __forceinline__ float lo2(ull p) { return __uint_as_float((uint)p); }
__device__ __forceinline__ float hi2(ull p) { return __uint_as_float((uint)(p >> 32)); }

__device__ __forceinline__ float hat_cdf(float t) {
    if (t <= -1.f) return 0.f;
    if (t <= 0.f) { float u = t + 1.f; return 0.5f * u * u; }
    if (t <= 1.f) { float u = 1.f - t; return 1.f - 0.5f * u * u; }
    return 1.f;
}

// ================= kernel 1: pool (R8-lineage verbatim) =================
__global__ __launch_bounds__(256) void pool_kernel(
    const float* __restrict__ X, const float* __restrict__ sb)
{
    __shared__ float s_wx[BB * 32];
    __shared__ float s_wy[BB * 16];
    __shared__ int   s_hlo[BB];
    __shared__ int   s_hlen[BB];

    const int t = threadIdx.x;
    const int wid = t >> 5, lane = t & 31;

    for (int e = t; e < BB * 32; e += 256) {
        const int b = e >> 5, w = e & 31;
        float x0 = sb[b * 4 + 0] * (float)HW;
        float x1 = sb[b * 4 + 2] * (float)HW;
        float v = 0.f;
        if (w < HW) v = hat_cdf(x1 - (float)w) - hat_cdf(x0 - (float)w);
        s_wx[e] = v;
    }
    for (int e = t; e < BB * 16; e += 256) {
        const int b = e >> 4, i = e & 15;
        float x0 = sb[b * 4 + 0] * (float)HW;
        float y0 = sb[b * 4 + 1] * (float)HW;
        float x1 = sb[b * 4 + 2] * (float)HW;
        float y1 = sb[b * 4 + 3] * (float)HW;
        float scale = 1.f / ((x1 - x0) * (y1 - y0));
        int hlo = max(0, (int)floorf(y0 - 1.f) + 1);
        int hhi = min(HW - 1, (int)ceilf(y1 + 1.f) - 1);
        if (i == 0) { s_hlo[b] = hlo; s_hlen[b] = hhi - hlo + 1; }
        int h = hlo + i;
        float v = 0.f;
        if (h <= hhi)
            v = (hat_cdf(y1 - (float)h) - hat_cdf(y0 - (float)h)) * scale;
        s_wy[e] = v;
    }
    __syncthreads();

    const int it = blockIdx.x * 8 + wid;
    if (it >= NIT8) return;
    const int b = it / 96;
    const int c0 = b * CC + (it - b * 96) * 8;
    const int hl = s_hlo[b], n = s_hlen[b];
    const float* base = X + (size_t)c0 * NPIX + hl * HW + lane;
    const float* wyp = s_wy + b * 16;

    float a0 = 0.f, a1 = 0.f, a2 = 0.f, a3 = 0.f;
    float a4 = 0.f, a5 = 0.f, a6 = 0.f, a7 = 0.f;
    if (lane < HW) {
        int off = 0;
        #pragma unroll 2
        for (int i = 0; i < n; i++, off += HW) {
            const float wy = wyp[i];
            const float* p = base + off;
            a0 = fmaf(wy, __ldg(p + 0 * NPIX), a0);
            a1 = fmaf(wy, __ldg(p + 1 * NPIX), a1);
            a2 = fmaf(wy, __ldg(p + 2 * NPIX), a2);
            a3 = fmaf(wy, __ldg(p + 3 * NPIX), a3);
            a4 = fmaf(wy, __ldg(p + 4 * NPIX), a4);
            a5 = fmaf(wy, __ldg(p + 5 * NPIX), a5);
            a6 = fmaf(wy, __ldg(p + 6 * NPIX), a6);
            a7 = fmaf(wy, __ldg(p + 7 * NPIX), a7);
        }
        const float wx = s_wx[b * 32 + lane];
        a0 *= wx; a1 *= wx; a2 *= wx; a3 *= wx;
        a4 *= wx; a5 *= wx; a6 *= wx; a7 *= wx;
    }
    ull p0 = pack2(a0, a1), p1 = pack2(a2, a3);
    ull p2 = pack2(a4, a5), p3 = pack2(a6, a7);
    #pragma unroll
    for (int sh = 16; sh; sh >>= 1) {
        p0 = fadd2(p0, __shfl_xor_sync(0xffffffffu, p0, sh));
        p1 = fadd2(p1, __shfl_xor_sync(0xffffffffu, p1, sh));
        p2 = fadd2(p2, __shfl_xor_sync(0xffffffffu, p2, sh));
        p3 = fadd2(p3, __shfl_xor_sync(0xffffffffu, p3, sh));
    }
    if (lane == 0) {
        g_featp[c0 + 0] = dup2(lo2(p0));
        g_featp[c0 + 1] = dup2(hi2(p0));
        g_featp[c0 + 2] = dup2(lo2(p1));
        g_featp[c0 + 3] = dup2(hi2(p1));
        g_featp[c0 + 4] = dup2(lo2(p2));
        g_featp[c0 + 5] = dup2(hi2(p2));
        g_featp[c0 + 6] = dup2(lo2(p3));
        g_featp[c0 + 7] = dup2(hi2(p3));
    }
}

// ================= kernel 2: GEMM1 (feat @ w1 -> p1 partials) =============
// grid (6, 12): x = 128-col tile, y = k-chunk KC1=64. 256 thr = 8 warps.
// warp = 8 rows x 128 cols; lane = 4 cols. W staged in 32KB smem;
// A (packed feat) via lane-uniform broadcast LDG.
__global__ __launch_bounds__(256, 2) void gemm1_kernel(
    const float* __restrict__ W, float* __restrict__ P)
{
    __shared__ __align__(16) float s_W[KC1 * 128];   // 32KB

    const int t = threadIdx.x;
    const int c0 = blockIdx.x * 128;
    const int k0 = blockIdx.y * KC1;

    // stage W [KC1 x 128]: 2048 float4, 8 per thread, coalesced
    #pragma unroll
    for (int j = 0; j < 8; j++) {
        const int e = t + j * 256;
        const int row = e >> 5, col4 = (e & 31) << 2;
        *(float4*)&s_W[row * 128 + col4] =
            *(const float4*)(W + (size_t)(k0 + row) * HID + c0 + col4);
    }
    __syncthreads();

    const int wid = t >> 5, lane = t & 31;
    const ull* ar = g_featp + (size_t)(wid * 8) * HID + k0;   // lane-uniform
    const float* wl = s_W + lane * 4;

    ulonglong2 acc[8];
    #pragma unroll
    for (int r = 0; r < 8; r++) acc[r] = make_ulonglong2(0ull, 0ull);

    #pragma unroll 4
    for (int k = 0; k < KC1; k += 2) {
        ulonglong2 w0 = *(const ulonglong2*)(wl + (size_t)k * 128);
        ulonglong2 w1 = *(const ulonglong2*)(wl + (size_t)(k + 1) * 128);
        #pragma unroll
        for (int r = 0; r < 8; r++) {
            ulonglong2 a2 = *(const ulonglong2*)(ar + (size_t)r * HID + k);
            acc[r].x = ffma2(a2.x, w0.x, acc[r].x);
            acc[r].y = ffma2(a2.x, w0.y, acc[r].y);
            acc[r].x = ffma2(a2.y, w1.x, acc[r].x);
            acc[r].y = ffma2(a2.y, w1.y, acc[r].y);
        }
    }

    float* op = P + (size_t)blockIdx.y * (BB * HID)
              + (size_t)(wid * 8) * HID + c0 + lane * 4;
    #pragma unroll
    for (int r = 0; r < 8; r++)
        *(ulonglong2*)(op + (size_t)r * HID) = acc[r];
}

// ================= kernel 3: GEMM2 with FUSED combine+bias+relu ===========
// grid (6, 24): x = 128-col tile, y = k-chunk KC2=32. 256 thr = 8 warps.
// A-tile staging computes act = relu(b1 + sum_z p1[z]) directly (the combine
// kernel is gone). W staged in 16KB smem; A packed in 16KB smem.
__global__ __launch_bounds__(256, 2) void gemm2_kernel(
    const float* __restrict__ b1, const float* __restrict__ W,
    float* __restrict__ P)
{
    __shared__ __align__(16) ull   s_A[64 * KC2];    // 16KB packed (a,a)
    __shared__ __align__(16) float s_W[KC2 * 128];   // 16KB

    const int t = threadIdx.x;
    const int c0 = blockIdx.x * 128;
    const int k0 = blockIdx.y * KC2;

    // stage W [KC2 x 128]: 1024 float4, 4 per thread
    #pragma unroll
    for (int j = 0; j < 4; j++) {
        const int e = t + j * 256;
        const int row = e >> 5, col4 = (e & 31) << 2;
        *(float4*)&s_W[row * 128 + col4] =
            *(const float4*)(W + (size_t)(k0 + row) * HID + c0 + col4);
    }
    // stage A with fused combine: 2048 elements, 8 per thread.
    // e -> (row = e>>5, k = e&31); lanes cover consecutive k (coalesced).
    #pragma unroll
    for (int j = 0; j < 8; j++) {
        const int e = t + j * 256;
        const int row = e >> 5, k = e & 31;
        const int idx = row * HID + k0 + k;
        float v = b1[k0 + k];
        #pragma unroll
        for (int z = 0; z < KS1; z++) v += g_p1[z][idx];
        s_A[row * KC2 + k] = dup2(fmaxf(v, 0.f));
    }
    __syncthreads();

    const int wid = t >> 5, lane = t & 31;
    const ull* ar = s_A + (wid * 8) * KC2;
    const float* wl = s_W + lane * 4;

    ulonglong2 acc[8];
    #pragma unroll
    for (int r = 0; r < 8; r++) acc[r] = make_ulonglong2(0ull, 0ull);

    #pragma unroll 4
    for (int k = 0; k < KC2; k += 2) {
        ulonglong2 w0 = *(const ulonglong2*)(wl + (size_t)k * 128);
        ulonglong2 w1 = *(const ulonglong2*)(wl + (size_t)(k + 1) * 128);
        #pragma unroll
        for (int r = 0; r < 8; r++) {
            ulonglong2 a2 = *(const ulonglong2*)(ar + r * KC2 + k);
            acc[r].x = ffma2(a2.x, w0.x, acc[r].x);
            acc[r].y = ffma2(a2.x, w0.y, acc[r].y);
            acc[r].x = ffma2(a2.y, w1.x, acc[r].x);
            acc[r].y = ffma2(a2.y, w1.y, acc[r].y);
        }
    }

    float* op = P + (size_t)blockIdx.y * (BB * HID)
              + (size_t)(wid * 8) * HID + c0 + lane * 4;
    #pragma unroll
    for (int r = 0; r < 8; r++)
        *(ulonglong2*)(op + (size_t)r * HID) = acc[r];
}

// ================= kernel 4: final combine + dot(w3) =================
__global__ __launch_bounds__(256) void final_kernel(
    const float* __restrict__ b2, const float* __restrict__ w3,
    const float* __restrict__ b3, float* __restrict__ out)
{
    __shared__ float red[8];
    const int b = blockIdx.x, t = threadIdx.x;
    const int wid = t >> 5, lane = t & 31;
    float acc = 0.f;
    #pragma unroll
    for (int j = 0; j < 3; j++) {
        const int k = t + j * 256;
        const int idx = b * HID + k;
        float v = b2[k];
        #pragma unroll
        for (int z = 0; z < KS2; z++) v += g_p2[z][idx];
        acc = fmaf(fmaxf(v, 0.f), w3[k], acc);
    }
    #pragma unroll
    for (int sh = 16; sh; sh >>= 1) acc += __shfl_xor_sync(0xffffffffu, acc, sh);
    if (lane == 0) red[wid] = acc;
    __syncthreads();
    if (t == 0) {
        float r = red[0] + red[1] + red[2] + red[3] +
                  red[4] + red[5] + red[6] + red[7];
        out[b] = r + b3[0];
    }
}

// ---------------- launch ----------------
extern "C" void kernel_launch(void* const* d_in, const int* in_sizes, int n_in,
                              void* d_out, int out_size) {
    const float* X  = (const float*)d_in[0];
    const float* sb = (const float*)d_in[1];
    const float* w1 = (const float*)d_in[2];
    const float* b1 = (const float*)d_in[3];
    const float* w2 = (const float*)d_in[4];
    const float* b2 = (const float*)d_in[5];
    const float* w3 = (const float*)d_in[6];
    const float* b3 = (const float*)d_in[7];
    float* out = (float*)d_out;

    float* p1; cudaGetSymbolAddress((void**)&p1, g_p1);
    float* p2; cudaGetSymbolAddress((void**)&p2, g_p2);

    pool_kernel<<<768, 256>>>(X, sb);
    gemm1_kernel<<<dim3(6, 12), 256>>>(w1, p1);
    gemm2_kernel<<<dim3(6, 24), 256>>>(b1, w2, p2);
    final_kernel<<<64, 256>>>(b2, w3, b3, out);
}